// round 7
// baseline (speedup 1.0000x reference)
#include <cuda_runtime.h>
#include <math.h>

#define NN 50000
#define EE 800000
#define EA (EE + NN)   // edges + self loops
#define NG 256

// ---------------- scratch ----------------
__device__ __align__(16) float g_h1[NN * 64];     // layer1 transformed features
__device__ __align__(16) float g_out1[NN * 64];   // layer1 output (post bias+elu)
__device__ __align__(16) float g_agg[NN * 64];    // layer2 aggregated (64-dim, pre-W2)
__device__ __align__(16) float g_ssrc1[NN * 4], g_sdst1[NN * 4];
__device__ float g_ssrc2[NN], g_sdst2[NN];
__device__ float g_va[64], g_vd[64];
__device__ __align__(16) float g_poolpart[4][NG * 256];
__device__ float g_z1[NG * 512];
__device__ float g_z2[NG * 1024];
__device__ __align__(16) float g_w[EA * 4];       // per-edge exp-weight staging
// CSR
__device__ int g_cnt[NN];
__device__ int g_row[NN + 1];
__device__ int g_csrc[EA];

// ---------------- helpers ----------------
__device__ __forceinline__ float lrelu(float x) { return x > 0.0f ? x : 0.2f * x; }
__device__ __forceinline__ float elu(float x)  { return x > 0.0f ? x : __expf(x) - 1.0f; }

__device__ __forceinline__ void edge_sd(const int* __restrict__ ei, int e, int& src, int& dst) {
    if (e < EE) { src = ei[e]; dst = ei[EE + e]; }
    else        { src = e - EE; dst = src; }
}

// ---------------- CSR build ----------------
__global__ void k_hist(const int* __restrict__ ei) {
    int e = blockIdx.x * blockDim.x + threadIdx.x;
    if (e >= EA) return;
    int src, dst; edge_sd(ei, e, src, dst);
    atomicAdd(&g_cnt[dst], 1);
}
#define SCAN_T 1024
#define SCAN_CH ((NN + SCAN_T - 1) / SCAN_T)   // 49
__global__ void k_scan() {
    int tid = threadIdx.x;
    int base = tid * SCAN_CH;
    int local = 0;
#pragma unroll
    for (int i = 0; i < SCAN_CH; i++) { int idx = base + i; if (idx < NN) local += g_cnt[idx]; }
    __shared__ int wsum[32];
    int lane = tid & 31, wid = tid >> 5;
    int v = local;
#pragma unroll
    for (int o = 1; o < 32; o <<= 1) { int t = __shfl_up_sync(~0u, v, o); if (lane >= o) v += t; }
    if (lane == 31) wsum[wid] = v;
    __syncthreads();
    if (wid == 0) {
        int w = wsum[lane];
#pragma unroll
        for (int o = 1; o < 32; o <<= 1) { int t = __shfl_up_sync(~0u, w, o); if (lane >= o) w += t; }
        wsum[lane] = w;
    }
    __syncthreads();
    int pref = (v - local) + (wid > 0 ? wsum[wid - 1] : 0);
    int run = pref;
    for (int i = 0; i < SCAN_CH; i++) {
        int idx = base + i;
        if (idx < NN) {
            int c = g_cnt[idx];
            g_row[idx] = run;
            g_cnt[idx] = run;   // cursor for scatter
            run += c;
        }
    }
    if (tid == SCAN_T - 1) g_row[NN] = EA;
}
__global__ void k_scatter(const int* __restrict__ ei) {
    int e = blockIdx.x * blockDim.x + threadIdx.x;
    if (e >= EA) return;
    int src, dst; edge_sd(ei, e, src, dst);
    int pos = atomicAdd(&g_cnt[dst], 1);
    g_csrc[pos] = src;
}

// ---------------- layer 1 ----------------
// h1 = x @ W1 with in-thread s1 scores; thread = (node, head) owning 16 channels
__global__ void k_lin1(const float* __restrict__ x, const float* __restrict__ W1,
                       const float* __restrict__ as, const float* __restrict__ ad) {
    __shared__ float W1s[27 * 64];
    __shared__ float xs[64 * 27];
    __shared__ float ass[64], ads[64];
    int tid = threadIdx.x;
    for (int i = tid; i < 27 * 64; i += 256) W1s[i] = W1[i];
    if (tid < 64) { ass[tid] = as[tid]; ads[tid] = ad[tid]; }
    long long base = (long long)blockIdx.x * 64 * 27;
    for (int i = tid; i < 64 * 27; i += 256) {
        long long gi = base + i;
        xs[i] = (gi < (long long)NN * 27) ? x[gi] : 0.0f;
    }
    __syncthreads();
    int nl = tid >> 2, h = tid & 3;
    int n = blockIdx.x * 64 + nl;
    if (n >= NN) return;
    float4 acc[4];
#pragma unroll
    for (int q = 0; q < 4; q++) acc[q] = make_float4(0.f, 0.f, 0.f, 0.f);
    const float4* W4 = (const float4*)W1s;
    const float* xr = xs + nl * 27;
#pragma unroll 9
    for (int k = 0; k < 27; k++) {
        float xv = xr[k];
        int wb = (k * 64 + h * 16) >> 2;
#pragma unroll
        for (int q = 0; q < 4; q++) {
            float4 w = W4[wb + q];
            acc[q].x += xv * w.x; acc[q].y += xv * w.y;
            acc[q].z += xv * w.z; acc[q].w += xv * w.w;
        }
    }
    float4* h1v = (float4*)g_h1;
#pragma unroll
    for (int q = 0; q < 4; q++) h1v[n * 16 + h * 4 + q] = acc[q];
    // in-thread s1 dots (16 channels of head h)
    const float4* a4s = (const float4*)ass;
    const float4* a4d = (const float4*)ads;
    float ps = 0.f, pd = 0.f;
#pragma unroll
    for (int q = 0; q < 4; q++) {
        float4 av = a4s[h * 4 + q];
        ps += acc[q].x * av.x + acc[q].y * av.y + acc[q].z * av.z + acc[q].w * av.w;
        float4 dv = a4d[h * 4 + q];
        pd += acc[q].x * dv.x + acc[q].y * dv.y + acc[q].z * dv.z + acc[q].w * dv.w;
    }
    g_ssrc1[n * 4 + h] = ps;
    g_sdst1[n * 4 + h] = pd;
}

// va = W2 @ a_src2, vd = W2 @ a_dst2; warp per (k, vec)
__global__ void k_vavd(const float* __restrict__ W2, const float* __restrict__ as,
                       const float* __restrict__ ad) {
    int w = (blockIdx.x * blockDim.x + threadIdx.x) >> 5;   // 0..127
    int lane = threadIdx.x & 31;
    if (w >= 128) return;
    int k = w >> 1;
    const float* vec = (w & 1) ? ad : as;
    float acc = 0.0f;
#pragma unroll
    for (int j = lane; j < 256; j += 32) acc += __ldg(&W2[k * 256 + j]) * __ldg(&vec[j]);
#pragma unroll
    for (int o = 16; o; o >>= 1) acc += __shfl_xor_sync(~0u, acc, o);
    if (lane == 0) { if (w & 1) g_vd[k] = acc; else g_va[k] = acc; }
}

// warp per node: no-max softmax + half-warp-per-edge broadcast-load aggregation
__global__ void k_gat1(const float* __restrict__ b1) {
    int n = (blockIdx.x * blockDim.x + threadIdx.x) >> 5;
    int lane = threadIdx.x & 31;
    int half = lane >> 4, hl = lane & 15, hh = hl >> 2;
    if (n >= NN) return;
    int beg = g_row[n], end = g_row[n + 1];
    const float4 sd = ((const float4*)g_sdst1)[n];

    // pass 1: gather ssrc once, stage w=exp(logit), accumulate sums
    float s0 = 1e-16f, s1 = 1e-16f, s2 = 1e-16f, s3 = 1e-16f;
    for (int e = beg + lane; e < end; e += 32) {
        int sc = __ldg(&g_csrc[e]);
        float4 ss = ((const float4*)g_ssrc1)[sc];
        float4 a;
        a.x = __expf(lrelu(ss.x + sd.x)); a.y = __expf(lrelu(ss.y + sd.y));
        a.z = __expf(lrelu(ss.z + sd.z)); a.w = __expf(lrelu(ss.w + sd.w));
        ((float4*)g_w)[e] = a;
        s0 += a.x; s1 += a.y; s2 += a.z; s3 += a.w;
    }
#pragma unroll
    for (int o = 16; o; o >>= 1) {
        s0 += __shfl_xor_sync(~0u, s0, o);
        s1 += __shfl_xor_sync(~0u, s1, o);
        s2 += __shfl_xor_sync(~0u, s2, o);
        s3 += __shfl_xor_sync(~0u, s3, o);
    }
    float i0 = 1.0f / s0, i1 = 1.0f / s1, i2 = 1.0f / s2, i3 = 1.0f / s3;

    // pass 2: half-warp per edge; uniform broadcast loads, no shuffles
    const float4* h1v = (const float4*)g_h1;
    float4 acc = make_float4(0.f, 0.f, 0.f, 0.f);
    for (int e = beg + half; e < end; e += 2) {
        int s = __ldg(&g_csrc[e]);
        float wv = g_w[e * 4 + hh];
        float4 hv = h1v[s * 16 + hl];
        acc.x += wv * hv.x; acc.y += wv * hv.y;
        acc.z += wv * hv.z; acc.w += wv * hv.w;
    }
    // combine halves, normalize
    acc.x += __shfl_xor_sync(~0u, acc.x, 16);
    acc.y += __shfl_xor_sync(~0u, acc.y, 16);
    acc.z += __shfl_xor_sync(~0u, acc.z, 16);
    acc.w += __shfl_xor_sync(~0u, acc.w, 16);
    float iv = (hh == 0) ? i0 : (hh == 1) ? i1 : (hh == 2) ? i2 : i3;
    acc.x *= iv; acc.y *= iv; acc.z *= iv; acc.w *= iv;

    float4 bb = __ldg(&((const float4*)b1)[hl]);
    float4 o;
    o.x = elu(acc.x + bb.x); o.y = elu(acc.y + bb.y);
    o.z = elu(acc.z + bb.z); o.w = elu(acc.w + bb.w);
    if (half == 0) ((float4*)g_out1)[n * 16 + hl] = o;

    // fused layer-2 scores: s_src2 = out1·va, s_dst2 = out1·vd
    float4 va = __ldg(&((const float4*)g_va)[hl]);
    float4 vd = __ldg(&((const float4*)g_vd)[hl]);
    float ps = o.x * va.x + o.y * va.y + o.z * va.z + o.w * va.w;
    float pd = o.x * vd.x + o.y * vd.y + o.z * vd.z + o.w * vd.w;
#pragma unroll
    for (int off = 8; off; off >>= 1) {
        ps += __shfl_xor_sync(~0u, ps, off);
        pd += __shfl_xor_sync(~0u, pd, off);
    }
    if (lane == 0) { g_ssrc2[n] = ps; g_sdst2[n] = pd; }
}

// warp per node: no-max softmax + half-warp-per-edge broadcast-load aggregation
__global__ void k_gat2() {
    int n = (blockIdx.x * blockDim.x + threadIdx.x) >> 5;
    int lane = threadIdx.x & 31;
    int half = lane >> 4, hl = lane & 15;
    if (n >= NN) return;
    int beg = g_row[n], end = g_row[n + 1];
    float sdv = g_sdst2[n];

    float ssum = 1e-16f;
    for (int e = beg + lane; e < end; e += 32) {
        int sc = __ldg(&g_csrc[e]);
        float w = __expf(lrelu(__ldg(&g_ssrc2[sc]) + sdv));
        g_w[e] = w;
        ssum += w;
    }
#pragma unroll
    for (int o = 16; o; o >>= 1) ssum += __shfl_xor_sync(~0u, ssum, o);
    float inv = 1.0f / ssum;

    const float4* ov = (const float4*)g_out1;
    float4 acc = make_float4(0.f, 0.f, 0.f, 0.f);
    for (int e = beg + half; e < end; e += 2) {
        int s = __ldg(&g_csrc[e]);
        float wv = g_w[e];
        float4 hv = ov[s * 16 + hl];
        acc.x += wv * hv.x; acc.y += wv * hv.y;
        acc.z += wv * hv.z; acc.w += wv * hv.w;
    }
    acc.x += __shfl_xor_sync(~0u, acc.x, 16);
    acc.y += __shfl_xor_sync(~0u, acc.y, 16);
    acc.z += __shfl_xor_sync(~0u, acc.z, 16);
    acc.w += __shfl_xor_sync(~0u, acc.w, 16);
    acc.x *= inv; acc.y *= inv; acc.z *= inv; acc.w *= inv;
    if (half == 0) ((float4*)g_agg)[n * 16 + hl] = acc;
}

// partial pool: poolpart[seg][g, j] = max_{n in seg}(agg[n] @ W2[:, j] + b2[j])
// grid (NG, 2, 4), 128 threads; elu deferred to mlp1 (monotonic)
__global__ void k_lin2pool(const float* __restrict__ W2, const float* __restrict__ b2) {
    int g = blockIdx.x;
    int tid = threadIdx.x;
    int j = blockIdx.y * 128 + tid;
    float w[64];
#pragma unroll
    for (int k = 0; k < 64; k++) w[k] = __ldg(&W2[k * 256 + j]);
    float bj = __ldg(&b2[j]);
    int n0 = (g * NN + NG - 1) / NG;
    int n1 = ((g + 1) * NN + NG - 1) / NG;
    int chunk = (n1 - n0 + 3) >> 2;
    int s0 = n0 + blockIdx.z * chunk;
    int s1 = min(n1, s0 + chunk);
    const float4* aggv = (const float4*)g_agg;
    float mx = -1e30f;
    for (int n = s0; n < s1; n++) {
        float acc = bj;
#pragma unroll
        for (int k = 0; k < 16; k++) {
            float4 rv = __ldg(&aggv[n * 16 + k]);
            acc += rv.x * w[4 * k] + rv.y * w[4 * k + 1]
                 + rv.z * w[4 * k + 2] + rv.w * w[4 * k + 3];
        }
        mx = fmaxf(mx, acc);
    }
    g_poolpart[blockIdx.z][g * 256 + j] = mx;
}

// ---------------- MLP ----------------
__global__ void k_mlp1(const float* __restrict__ W, const float* __restrict__ b) {
    __shared__ float As[8 * 256];
    int g0 = blockIdx.x * 8;
    int tid = threadIdx.x;
    for (int idx = tid; idx < 8 * 256; idx += 256) {
        int gi = g0 * 256 + idx;
        float p = fmaxf(fmaxf(g_poolpart[0][gi], g_poolpart[1][gi]),
                        fmaxf(g_poolpart[2][gi], g_poolpart[3][gi]));
        As[idx] = elu(p);
    }
    __syncthreads();
    int j = blockIdx.y * 256 + tid;
    float bj = __ldg(&b[j]);
    float acc[8];
#pragma unroll
    for (int g = 0; g < 8; g++) acc[g] = bj;
    for (int k = 0; k < 256; k++) {
        float w = __ldg(&W[k * 512 + j]);
#pragma unroll
        for (int g = 0; g < 8; g++) acc[g] += As[g * 256 + k] * w;
    }
#pragma unroll
    for (int g = 0; g < 8; g++) g_z1[(g0 + g) * 512 + j] = fmaxf(acc[g], 0.0f);
}

__global__ void k_mlp2(const float* __restrict__ W, const float* __restrict__ b) {
    __shared__ float As[8 * 512];
    int g0 = blockIdx.x * 8;
    int tid = threadIdx.x;
    for (int idx = tid; idx < 8 * 512; idx += 256) As[idx] = g_z1[g0 * 512 + idx];
    __syncthreads();
    int j = blockIdx.y * 256 + tid;
    float bj = __ldg(&b[j]);
    float acc[8];
#pragma unroll
    for (int g = 0; g < 8; g++) acc[g] = bj;
    for (int k = 0; k < 512; k++) {
        float w = __ldg(&W[k * 1024 + j]);
#pragma unroll
        for (int g = 0; g < 8; g++) acc[g] += As[g * 512 + k] * w;
    }
#pragma unroll
    for (int g = 0; g < 8; g++) g_z2[(g0 + g) * 1024 + j] = fmaxf(acc[g], 0.0f);
}

__global__ void k_mlp3(const float* __restrict__ W, const float* __restrict__ b,
                       float* __restrict__ out) {
    int o = (blockIdx.x * blockDim.x + threadIdx.x) >> 5;
    int lane = threadIdx.x & 31;
    if (o >= NG * 4) return;
    int g = o >> 2, j = o & 3;
    float acc = 0.f;
    for (int k = lane; k < 1024; k += 32) acc += g_z2[g * 1024 + k] * __ldg(&W[k * 4 + j]);
#pragma unroll
    for (int off = 16; off > 0; off >>= 1) acc += __shfl_down_sync(0xFFFFFFFF, acc, off);
    if (lane == 0) out[o] = acc + b[j];
}

// ---------------- launch ----------------
extern "C" void kernel_launch(void* const* d_in, const int* in_sizes, int n_in,
                              void* d_out, int out_size) {
    const float* x     = (const float*)d_in[0];
    const int*   ei    = (const int*)d_in[1];
    const float* W1    = (const float*)d_in[3];
    const float* as1   = (const float*)d_in[4];
    const float* ad1   = (const float*)d_in[5];
    const float* b1    = (const float*)d_in[6];
    const float* W2    = (const float*)d_in[7];
    const float* as2   = (const float*)d_in[8];
    const float* ad2   = (const float*)d_in[9];
    const float* b2    = (const float*)d_in[10];
    const float* Wl1   = (const float*)d_in[11];
    const float* bl1   = (const float*)d_in[12];
    const float* Wl2   = (const float*)d_in[13];
    const float* bl2   = (const float*)d_in[14];
    const float* Wl3   = (const float*)d_in[15];
    const float* bl3   = (const float*)d_in[16];
    float* out = (float*)d_out;

    const int B = 256;
    auto cdiv = [](long long a, long long b) { return (int)((a + b - 1) / b); };

    // CSR build (dst-sorted)
    void* cntp = nullptr;
    cudaGetSymbolAddress(&cntp, g_cnt);
    cudaMemsetAsync(cntp, 0, NN * sizeof(int));
    k_hist<<<cdiv(EA, B), B>>>(ei);
    k_scan<<<1, SCAN_T>>>();
    k_scatter<<<cdiv(EA, B), B>>>(ei);

    // layer 1 (+ fused s1 + fused layer-2 scores)
    k_lin1<<<cdiv(NN, 64), B>>>(x, W1, as1, ad1);
    k_vavd<<<16, B>>>(W2, as2, ad2);
    k_gat1<<<cdiv(NN, 8), B>>>(b1);

    // layer 2 (64-dim aggregation, then fused W2 + partial pool)
    k_gat2<<<cdiv(NN, 8), B>>>();
    k_lin2pool<<<dim3(NG, 2, 4), 128>>>(W2, b2);

    // MLP
    k_mlp1<<<dim3(NG / 8, 2), B>>>(Wl1, bl1);
    k_mlp2<<<dim3(NG / 8, 4), B>>>(Wl2, bl2);
    k_mlp3<<<cdiv(NG * 4 * 32, B), B>>>(Wl3, bl3, out);
}

// round 8
// speedup vs baseline: 1.0002x; 1.0002x over previous
#include <cuda_runtime.h>
#include <math.h>

#define NN 50000
#define EE 800000
#define EA (EE + NN)   // edges + self loops
#define NG 256

// ---------------- scratch ----------------
__device__ __align__(16) float g_h1[NN * 64];     // layer1 transformed features
__device__ __align__(16) float g_out1[NN * 64];   // layer1 output (post bias+elu)
__device__ __align__(16) float g_agg[NN * 64];    // layer2 aggregated (64-dim, pre-W2)
__device__ __align__(16) float g_ssrc1[NN * 4], g_sdst1[NN * 4];
__device__ float g_ssrc2[NN], g_sdst2[NN];
__device__ float g_va[64], g_vd[64];
__device__ __align__(16) float g_poolpart[4][NG * 256];
__device__ float g_z1[NG * 512];
__device__ float g_z2[NG * 1024];
__device__ __align__(16) float g_w[EA * 4];       // per-edge exp-weight staging
// CSR
__device__ int g_cnt[NN];
__device__ int g_row[NN + 1];
__device__ int g_csrc[EA];

// ---------------- helpers ----------------
__device__ __forceinline__ float lrelu(float x) { return x > 0.0f ? x : 0.2f * x; }
__device__ __forceinline__ float elu(float x)  { return x > 0.0f ? x : __expf(x) - 1.0f; }

__device__ __forceinline__ void edge_sd(const int* __restrict__ ei, int e, int& src, int& dst) {
    if (e < EE) { src = ei[e]; dst = ei[EE + e]; }
    else        { src = e - EE; dst = src; }
}

// ---------------- CSR build ----------------
__global__ void k_hist(const int* __restrict__ ei) {
    int e = blockIdx.x * blockDim.x + threadIdx.x;
    if (e >= EA) return;
    int src, dst; edge_sd(ei, e, src, dst);
    atomicAdd(&g_cnt[dst], 1);
}
#define SCAN_T 1024
#define SCAN_CH ((NN + SCAN_T - 1) / SCAN_T)   // 49
__global__ void k_scan() {
    int tid = threadIdx.x;
    int base = tid * SCAN_CH;
    int local = 0;
#pragma unroll
    for (int i = 0; i < SCAN_CH; i++) { int idx = base + i; if (idx < NN) local += g_cnt[idx]; }
    __shared__ int wsum[32];
    int lane = tid & 31, wid = tid >> 5;
    int v = local;
#pragma unroll
    for (int o = 1; o < 32; o <<= 1) { int t = __shfl_up_sync(~0u, v, o); if (lane >= o) v += t; }
    if (lane == 31) wsum[wid] = v;
    __syncthreads();
    if (wid == 0) {
        int w = wsum[lane];
#pragma unroll
        for (int o = 1; o < 32; o <<= 1) { int t = __shfl_up_sync(~0u, w, o); if (lane >= o) w += t; }
        wsum[lane] = w;
    }
    __syncthreads();
    int pref = (v - local) + (wid > 0 ? wsum[wid - 1] : 0);
    int run = pref;
    for (int i = 0; i < SCAN_CH; i++) {
        int idx = base + i;
        if (idx < NN) {
            int c = g_cnt[idx];
            g_row[idx] = run;
            g_cnt[idx] = run;   // cursor for scatter
            run += c;
        }
    }
    if (tid == SCAN_T - 1) g_row[NN] = EA;
}
__global__ void k_scatter(const int* __restrict__ ei) {
    int e = blockIdx.x * blockDim.x + threadIdx.x;
    if (e >= EA) return;
    int src, dst; edge_sd(ei, e, src, dst);
    int pos = atomicAdd(&g_cnt[dst], 1);
    g_csrc[pos] = src;
}

// ---------------- layer 1 ----------------
// h1 = x @ W1 with in-thread s1 scores; thread = (node, head) owning 16 channels
__global__ void k_lin1(const float* __restrict__ x, const float* __restrict__ W1,
                       const float* __restrict__ as, const float* __restrict__ ad) {
    __shared__ float W1s[27 * 64];
    __shared__ float xs[64 * 27];
    __shared__ float ass[64], ads[64];
    int tid = threadIdx.x;
    for (int i = tid; i < 27 * 64; i += 256) W1s[i] = W1[i];
    if (tid < 64) { ass[tid] = as[tid]; ads[tid] = ad[tid]; }
    long long base = (long long)blockIdx.x * 64 * 27;
    for (int i = tid; i < 64 * 27; i += 256) {
        long long gi = base + i;
        xs[i] = (gi < (long long)NN * 27) ? x[gi] : 0.0f;
    }
    __syncthreads();
    int nl = tid >> 2, h = tid & 3;
    int n = blockIdx.x * 64 + nl;
    if (n >= NN) return;
    float4 acc[4];
#pragma unroll
    for (int q = 0; q < 4; q++) acc[q] = make_float4(0.f, 0.f, 0.f, 0.f);
    const float4* W4 = (const float4*)W1s;
    const float* xr = xs + nl * 27;
#pragma unroll 9
    for (int k = 0; k < 27; k++) {
        float xv = xr[k];
        int wb = (k * 64 + h * 16) >> 2;
#pragma unroll
        for (int q = 0; q < 4; q++) {
            float4 w = W4[wb + q];
            acc[q].x += xv * w.x; acc[q].y += xv * w.y;
            acc[q].z += xv * w.z; acc[q].w += xv * w.w;
        }
    }
    float4* h1v = (float4*)g_h1;
#pragma unroll
    for (int q = 0; q < 4; q++) h1v[n * 16 + h * 4 + q] = acc[q];
    // in-thread s1 dots (16 channels of head h)
    const float4* a4s = (const float4*)ass;
    const float4* a4d = (const float4*)ads;
    float ps = 0.f, pd = 0.f;
#pragma unroll
    for (int q = 0; q < 4; q++) {
        float4 av = a4s[h * 4 + q];
        ps += acc[q].x * av.x + acc[q].y * av.y + acc[q].z * av.z + acc[q].w * av.w;
        float4 dv = a4d[h * 4 + q];
        pd += acc[q].x * dv.x + acc[q].y * dv.y + acc[q].z * dv.z + acc[q].w * dv.w;
    }
    g_ssrc1[n * 4 + h] = ps;
    g_sdst1[n * 4 + h] = pd;
}

// va = W2 @ a_src2, vd = W2 @ a_dst2; warp per (k, vec)
__global__ void k_vavd(const float* __restrict__ W2, const float* __restrict__ as,
                       const float* __restrict__ ad) {
    int w = (blockIdx.x * blockDim.x + threadIdx.x) >> 5;   // 0..127
    int lane = threadIdx.x & 31;
    if (w >= 128) return;
    int k = w >> 1;
    const float* vec = (w & 1) ? ad : as;
    float acc = 0.0f;
#pragma unroll
    for (int j = lane; j < 256; j += 32) acc += __ldg(&W2[k * 256 + j]) * __ldg(&vec[j]);
#pragma unroll
    for (int o = 16; o; o >>= 1) acc += __shfl_xor_sync(~0u, acc, o);
    if (lane == 0) { if (w & 1) g_vd[k] = acc; else g_va[k] = acc; }
}

// warp per node: no-max softmax + half-warp-per-edge broadcast-load aggregation
__global__ void k_gat1(const float* __restrict__ b1) {
    int n = (blockIdx.x * blockDim.x + threadIdx.x) >> 5;
    int lane = threadIdx.x & 31;
    int half = lane >> 4, hl = lane & 15, hh = hl >> 2;
    if (n >= NN) return;
    int beg = g_row[n], end = g_row[n + 1];
    const float4 sd = ((const float4*)g_sdst1)[n];

    // pass 1: gather ssrc once, stage w=exp(logit), accumulate sums
    float s0 = 1e-16f, s1 = 1e-16f, s2 = 1e-16f, s3 = 1e-16f;
    for (int e = beg + lane; e < end; e += 32) {
        int sc = __ldg(&g_csrc[e]);
        float4 ss = ((const float4*)g_ssrc1)[sc];
        float4 a;
        a.x = __expf(lrelu(ss.x + sd.x)); a.y = __expf(lrelu(ss.y + sd.y));
        a.z = __expf(lrelu(ss.z + sd.z)); a.w = __expf(lrelu(ss.w + sd.w));
        ((float4*)g_w)[e] = a;
        s0 += a.x; s1 += a.y; s2 += a.z; s3 += a.w;
    }
#pragma unroll
    for (int o = 16; o; o >>= 1) {
        s0 += __shfl_xor_sync(~0u, s0, o);
        s1 += __shfl_xor_sync(~0u, s1, o);
        s2 += __shfl_xor_sync(~0u, s2, o);
        s3 += __shfl_xor_sync(~0u, s3, o);
    }
    float i0 = 1.0f / s0, i1 = 1.0f / s1, i2 = 1.0f / s2, i3 = 1.0f / s3;

    // pass 2: half-warp per edge; uniform broadcast loads, no shuffles
    const float4* h1v = (const float4*)g_h1;
    float4 acc = make_float4(0.f, 0.f, 0.f, 0.f);
    for (int e = beg + half; e < end; e += 2) {
        int s = __ldg(&g_csrc[e]);
        float wv = g_w[e * 4 + hh];
        float4 hv = h1v[s * 16 + hl];
        acc.x += wv * hv.x; acc.y += wv * hv.y;
        acc.z += wv * hv.z; acc.w += wv * hv.w;
    }
    // combine halves, normalize
    acc.x += __shfl_xor_sync(~0u, acc.x, 16);
    acc.y += __shfl_xor_sync(~0u, acc.y, 16);
    acc.z += __shfl_xor_sync(~0u, acc.z, 16);
    acc.w += __shfl_xor_sync(~0u, acc.w, 16);
    float iv = (hh == 0) ? i0 : (hh == 1) ? i1 : (hh == 2) ? i2 : i3;
    acc.x *= iv; acc.y *= iv; acc.z *= iv; acc.w *= iv;

    float4 bb = __ldg(&((const float4*)b1)[hl]);
    float4 o;
    o.x = elu(acc.x + bb.x); o.y = elu(acc.y + bb.y);
    o.z = elu(acc.z + bb.z); o.w = elu(acc.w + bb.w);
    if (half == 0) ((float4*)g_out1)[n * 16 + hl] = o;

    // fused layer-2 scores: s_src2 = out1·va, s_dst2 = out1·vd
    float4 va = __ldg(&((const float4*)g_va)[hl]);
    float4 vd = __ldg(&((const float4*)g_vd)[hl]);
    float ps = o.x * va.x + o.y * va.y + o.z * va.z + o.w * va.w;
    float pd = o.x * vd.x + o.y * vd.y + o.z * vd.z + o.w * vd.w;
#pragma unroll
    for (int off = 8; off; off >>= 1) {
        ps += __shfl_xor_sync(~0u, ps, off);
        pd += __shfl_xor_sync(~0u, pd, off);
    }
    if (lane == 0) { g_ssrc2[n] = ps; g_sdst2[n] = pd; }
}

// warp per node: no-max softmax + half-warp-per-edge broadcast-load aggregation
__global__ void k_gat2() {
    int n = (blockIdx.x * blockDim.x + threadIdx.x) >> 5;
    int lane = threadIdx.x & 31;
    int half = lane >> 4, hl = lane & 15;
    if (n >= NN) return;
    int beg = g_row[n], end = g_row[n + 1];
    float sdv = g_sdst2[n];

    float ssum = 1e-16f;
    for (int e = beg + lane; e < end; e += 32) {
        int sc = __ldg(&g_csrc[e]);
        float w = __expf(lrelu(__ldg(&g_ssrc2[sc]) + sdv));
        g_w[e] = w;
        ssum += w;
    }
#pragma unroll
    for (int o = 16; o; o >>= 1) ssum += __shfl_xor_sync(~0u, ssum, o);
    float inv = 1.0f / ssum;

    const float4* ov = (const float4*)g_out1;
    float4 acc = make_float4(0.f, 0.f, 0.f, 0.f);
    for (int e = beg + half; e < end; e += 2) {
        int s = __ldg(&g_csrc[e]);
        float wv = g_w[e];
        float4 hv = ov[s * 16 + hl];
        acc.x += wv * hv.x; acc.y += wv * hv.y;
        acc.z += wv * hv.z; acc.w += wv * hv.w;
    }
    acc.x += __shfl_xor_sync(~0u, acc.x, 16);
    acc.y += __shfl_xor_sync(~0u, acc.y, 16);
    acc.z += __shfl_xor_sync(~0u, acc.z, 16);
    acc.w += __shfl_xor_sync(~0u, acc.w, 16);
    acc.x *= inv; acc.y *= inv; acc.z *= inv; acc.w *= inv;
    if (half == 0) ((float4*)g_agg)[n * 16 + hl] = acc;
}

// partial pool: poolpart[seg][g, j] = max_{n in seg}(agg[n] @ W2[:, j] + b2[j])
// grid (NG, 2, 4), 128 threads; elu deferred to mlp1 (monotonic)
__global__ void k_lin2pool(const float* __restrict__ W2, const float* __restrict__ b2) {
    int g = blockIdx.x;
    int tid = threadIdx.x;
    int j = blockIdx.y * 128 + tid;
    float w[64];
#pragma unroll
    for (int k = 0; k < 64; k++) w[k] = __ldg(&W2[k * 256 + j]);
    float bj = __ldg(&b2[j]);
    int n0 = (g * NN + NG - 1) / NG;
    int n1 = ((g + 1) * NN + NG - 1) / NG;
    int chunk = (n1 - n0 + 3) >> 2;
    int s0 = n0 + blockIdx.z * chunk;
    int s1 = min(n1, s0 + chunk);
    const float4* aggv = (const float4*)g_agg;
    float mx = -1e30f;
    for (int n = s0; n < s1; n++) {
        float acc = bj;
#pragma unroll
        for (int k = 0; k < 16; k++) {
            float4 rv = __ldg(&aggv[n * 16 + k]);
            acc += rv.x * w[4 * k] + rv.y * w[4 * k + 1]
                 + rv.z * w[4 * k + 2] + rv.w * w[4 * k + 3];
        }
        mx = fmaxf(mx, acc);
    }
    g_poolpart[blockIdx.z][g * 256 + j] = mx;
}

// ---------------- MLP ----------------
__global__ void k_mlp1(const float* __restrict__ W, const float* __restrict__ b) {
    __shared__ float As[8 * 256];
    int g0 = blockIdx.x * 8;
    int tid = threadIdx.x;
    for (int idx = tid; idx < 8 * 256; idx += 256) {
        int gi = g0 * 256 + idx;
        float p = fmaxf(fmaxf(g_poolpart[0][gi], g_poolpart[1][gi]),
                        fmaxf(g_poolpart[2][gi], g_poolpart[3][gi]));
        As[idx] = elu(p);
    }
    __syncthreads();
    int j = blockIdx.y * 256 + tid;
    float bj = __ldg(&b[j]);
    float acc[8];
#pragma unroll
    for (int g = 0; g < 8; g++) acc[g] = bj;
    for (int k = 0; k < 256; k++) {
        float w = __ldg(&W[k * 512 + j]);
#pragma unroll
        for (int g = 0; g < 8; g++) acc[g] += As[g * 256 + k] * w;
    }
#pragma unroll
    for (int g = 0; g < 8; g++) g_z1[(g0 + g) * 512 + j] = fmaxf(acc[g], 0.0f);
}

__global__ void k_mlp2(const float* __restrict__ W, const float* __restrict__ b) {
    __shared__ float As[8 * 512];
    int g0 = blockIdx.x * 8;
    int tid = threadIdx.x;
    for (int idx = tid; idx < 8 * 512; idx += 256) As[idx] = g_z1[g0 * 512 + idx];
    __syncthreads();
    int j = blockIdx.y * 256 + tid;
    float bj = __ldg(&b[j]);
    float acc[8];
#pragma unroll
    for (int g = 0; g < 8; g++) acc[g] = bj;
    for (int k = 0; k < 512; k++) {
        float w = __ldg(&W[k * 1024 + j]);
#pragma unroll
        for (int g = 0; g < 8; g++) acc[g] += As[g * 512 + k] * w;
    }
#pragma unroll
    for (int g = 0; g < 8; g++) g_z2[(g0 + g) * 1024 + j] = fmaxf(acc[g], 0.0f);
}

__global__ void k_mlp3(const float* __restrict__ W, const float* __restrict__ b,
                       float* __restrict__ out) {
    int o = (blockIdx.x * blockDim.x + threadIdx.x) >> 5;
    int lane = threadIdx.x & 31;
    if (o >= NG * 4) return;
    int g = o >> 2, j = o & 3;
    float acc = 0.f;
    for (int k = lane; k < 1024; k += 32) acc += g_z2[g * 1024 + k] * __ldg(&W[k * 4 + j]);
#pragma unroll
    for (int off = 16; off > 0; off >>= 1) acc += __shfl_down_sync(0xFFFFFFFF, acc, off);
    if (lane == 0) out[o] = acc + b[j];
}

// ---------------- launch ----------------
extern "C" void kernel_launch(void* const* d_in, const int* in_sizes, int n_in,
                              void* d_out, int out_size) {
    const float* x     = (const float*)d_in[0];
    const int*   ei    = (const int*)d_in[1];
    const float* W1    = (const float*)d_in[3];
    const float* as1   = (const float*)d_in[4];
    const float* ad1   = (const float*)d_in[5];
    const float* b1    = (const float*)d_in[6];
    const float* W2    = (const float*)d_in[7];
    const float* as2   = (const float*)d_in[8];
    const float* ad2   = (const float*)d_in[9];
    const float* b2    = (const float*)d_in[10];
    const float* Wl1   = (const float*)d_in[11];
    const float* bl1   = (const float*)d_in[12];
    const float* Wl2   = (const float*)d_in[13];
    const float* bl2   = (const float*)d_in[14];
    const float* Wl3   = (const float*)d_in[15];
    const float* bl3   = (const float*)d_in[16];
    float* out = (float*)d_out;

    const int B = 256;
    auto cdiv = [](long long a, long long b) { return (int)((a + b - 1) / b); };

    // CSR build (dst-sorted)
    void* cntp = nullptr;
    cudaGetSymbolAddress(&cntp, g_cnt);
    cudaMemsetAsync(cntp, 0, NN * sizeof(int));
    k_hist<<<cdiv(EA, B), B>>>(ei);
    k_scan<<<1, SCAN_T>>>();
    k_scatter<<<cdiv(EA, B), B>>>(ei);

    // layer 1 (+ fused s1 + fused layer-2 scores)
    k_lin1<<<cdiv(NN, 64), B>>>(x, W1, as1, ad1);
    k_vavd<<<16, B>>>(W2, as2, ad2);
    k_gat1<<<cdiv(NN, 8), B>>>(b1);

    // layer 2 (64-dim aggregation, then fused W2 + partial pool)
    k_gat2<<<cdiv(NN, 8), B>>>();
    k_lin2pool<<<dim3(NG, 2, 4), 128>>>(W2, b2);

    // MLP
    k_mlp1<<<dim3(NG / 8, 2), B>>>(Wl1, bl1);
    k_mlp2<<<dim3(NG / 8, 4), B>>>(Wl2, bl2);
    k_mlp3<<<cdiv(NG * 4 * 32, B), B>>>(Wl3, bl3, out);
}